// round 10
// baseline (speedup 1.0000x reference)
#include <cuda_runtime.h>
#include <cstdint>

// out[n,d] = mean_f( x[n,f]*W[f,d] + b[f,d] ) = (x@W)[n,d]/256 + mean_f b[f,d]
// N=8192, K=256, D=64. bf16 3-term split on tensor cores (mma.sync m16n8k16).
// prep: W -> Wf fragment table (64KB) + mb. main (PDL): x LDGs -> wait ->
// Wf -> smem (overlapped with x convert) -> all-smem HMMA mainloop.

typedef uint32_t u32;

#define NROWS  8192
#define NF     256
#define ND     64
#define TILE_M 32
#define MTHREADS 256
#define NBLOCKS (NROWS / TILE_M)   // 256

#define XPITCHB (264 * 2)                       // 528B padded row
#define XH_OFF 0
#define XL_OFF (XH_OFF + TILE_M * XPITCHB)      // 16896
#define WF_OFF (XL_OFF + TILE_M * XPITCHB)      // 33792
#define WF_BYTES (16 * 64 * 4 * 16)             // 65536 (4096 uint4)
#define SMEM_BYTES (WF_OFF + WF_BYTES)          // 99328

// Wf[ki][col][t] : uint4 {hi(k=2t,2t+1), hi(k=2t+8,2t+9), lo(..), lo(..)}
__device__ uint4 Wf_g[16 * 64 * 4];
__device__ float mb_g[64];

__device__ __forceinline__ u32 smem_u32(const void* p) {
    u32 a;
    asm("{ .reg .u64 t; cvta.to.shared.u64 t, %1; cvt.u32.u64 %0, t; }" : "=r"(a) : "l"(p));
    return a;
}
__device__ __forceinline__ void cvt_split(float a, float b, u32& hi, u32& lo) {
    asm("cvt.rn.bf16x2.f32 %0, %1, %2;" : "=r"(hi) : "f"(b), "f"(a));
    float ha = __uint_as_float(hi << 16);
    float hb = __uint_as_float(hi & 0xFFFF0000u);
    float ra = a - ha;
    float rb = b - hb;
    asm("cvt.rn.bf16x2.f32 %0, %1, %2;" : "=r"(lo) : "f"(rb), "f"(ra));
}
__device__ __forceinline__ void ldsm4(u32* r, u32 addr) {
    asm volatile("ldmatrix.sync.aligned.m8n8.x4.shared.b16 {%0,%1,%2,%3}, [%4];"
        : "=r"(r[0]), "=r"(r[1]), "=r"(r[2]), "=r"(r[3]) : "r"(addr));
}
__device__ __forceinline__ void mma16816(float* c, const u32* a, u32 b0, u32 b1) {
    asm volatile(
        "mma.sync.aligned.m16n8k16.row.col.f32.bf16.bf16.f32 "
        "{%0,%1,%2,%3}, {%4,%5,%6,%7}, {%8,%9}, {%0,%1,%2,%3};"
        : "+f"(c[0]), "+f"(c[1]), "+f"(c[2]), "+f"(c[3])
        : "r"(a[0]), "r"(a[1]), "r"(a[2]), "r"(a[3]), "r"(b0), "r"(b1));
}

// ---------------- prep kernel ----------------
__global__ void __launch_bounds__(256)
prep_kernel(const float* __restrict__ W, const float* __restrict__ b)
{
    const int tid = threadIdx.x;
    if (blockIdx.x < 16) {
        int idx = blockIdx.x * 256 + tid;          // 0..4095
        int ki  = idx >> 8;
        int col = (idx >> 2) & 63;
        int t   = idx & 3;
        int k0  = ki * 16 + 2 * t;
        float w0 = W[(k0    ) * ND + col];
        float w1 = W[(k0 + 1) * ND + col];
        float w2 = W[(k0 + 8) * ND + col];
        float w3 = W[(k0 + 9) * ND + col];
        u32 h01, l01, h23, l23;
        cvt_split(w0, w1, h01, l01);
        cvt_split(w2, w3, h23, l23);
        Wf_g[idx] = make_uint4(h01, h23, l01, l23);
    } else {
        __shared__ float4 sc[256];
        const int qd = tid & 15;
        const int fr = tid >> 4;
        const float4* b4 = (const float4*)b;   // [256][16] float4
        float4 s = make_float4(0.f, 0.f, 0.f, 0.f);
        #pragma unroll
        for (int k = 0; k < 16; ++k) {
            float4 v = b4[(fr * 16 + k) * 16 + qd];
            s.x += v.x; s.y += v.y; s.z += v.z; s.w += v.w;
        }
        sc[tid] = s;
        __syncthreads();
        if (tid < 16) {
            float4 m = make_float4(0.f, 0.f, 0.f, 0.f);
            #pragma unroll
            for (int g = 0; g < 16; ++g) {
                float4 v = sc[tid + 16 * g];
                m.x += v.x; m.y += v.y; m.z += v.z; m.w += v.w;
            }
            const float inv = 1.f / 256.f;
            m.x *= inv; m.y *= inv; m.z *= inv; m.w *= inv;
            ((float4*)mb_g)[tid] = m;
        }
    }
    __threadfence();
    __syncthreads();
    asm volatile("griddepcontrol.launch_dependents;");
}

// ---------------- main kernel ----------------
__global__ void __launch_bounds__(MTHREADS, 2)
nanembed_hmma_kernel(const float* __restrict__ x, float* __restrict__ out)
{
    extern __shared__ char smem[];
    const u32 sb = smem_u32(smem);
    const int tid = threadIdx.x;
    const int bid = blockIdx.x;

    // ---- 1) issue x tile loads (DRAM) into registers ----
    float4 xv[8];
    {
        const float4* x4 = (const float4*)(x + (size_t)bid * TILE_M * NF);
        #pragma unroll
        for (int i = 0; i < 8; ++i)
            xv[i] = x4[tid + MTHREADS * i];
    }

    // ---- 2) PDL wait (x loads already in flight) ----
    asm volatile("griddepcontrol.wait;");

    // ---- 3) issue Wf half-1 loads (L2) into registers ----
    uint4* ws = (uint4*)(smem + WF_OFF);
    uint4 wv[8];
    #pragma unroll
    for (int i = 0; i < 8; ++i)
        wv[i] = Wf_g[tid + MTHREADS * i];

    // ---- 4) convert x -> XH/XL smem (covers Wf latency) ----
    #pragma unroll
    for (int i = 0; i < 8; ++i) {
        int idx = tid + MTHREADS * i;       // 0..2047
        int row = idx >> 6;                 // 0..31
        int c4  = idx & 63;
        u32 h0, l0, h1, l1;
        cvt_split(xv[i].x, xv[i].y, h0, l0);
        cvt_split(xv[i].z, xv[i].w, h1, l1);
        u32 off = (u32)(row * XPITCHB + c4 * 8);
        asm volatile("st.shared.v2.b32 [%0], {%1, %2};"
                     :: "r"(sb + XH_OFF + off), "r"(h0), "r"(h1) : "memory");
        asm volatile("st.shared.v2.b32 [%0], {%1, %2};"
                     :: "r"(sb + XL_OFF + off), "r"(l0), "r"(l1) : "memory");
    }

    // ---- 5) store half-1, then load/store half-2 of Wf ----
    #pragma unroll
    for (int i = 0; i < 8; ++i)
        ws[tid + MTHREADS * i] = wv[i];
    #pragma unroll
    for (int i = 0; i < 8; ++i)
        wv[i] = Wf_g[2048 + tid + MTHREADS * i];
    #pragma unroll
    for (int i = 0; i < 8; ++i)
        ws[2048 + tid + MTHREADS * i] = wv[i];
    __syncthreads();

    // ---- mainloop: warp = 16 rows x 16 cols, all operands in smem ----
    const int wid  = tid >> 5;
    const int lane = tid & 31;
    const int r0   = (wid & 1) * 16;
    const int n0   = (wid >> 1) * 16;
    const int g    = lane >> 2;
    const int t    = lane & 3;

    u32 aAddrH = sb + XH_OFF + (u32)(r0 + (lane & 15)) * XPITCHB + (u32)(lane >> 4) * 16;
    u32 aAddrL = aAddrH + (u32)(XL_OFF - XH_OFF);
    const uint4* bp0 = ws + ((n0 + g) * 4 + t);
    const uint4* bp1 = bp0 + 32;

    float a0hh[4] = {0,0,0,0}, a0hl[4] = {0,0,0,0}, a0lh[4] = {0,0,0,0};
    float a1hh[4] = {0,0,0,0}, a1hl[4] = {0,0,0,0}, a1lh[4] = {0,0,0,0};

    // 1-deep software pipeline
    u32 ah[2][4], al[2][4];
    uint4 b0[2], b1[2];
    ldsm4(ah[0], aAddrH);
    ldsm4(al[0], aAddrL);
    b0[0] = bp0[0];
    b1[0] = bp1[0];

    #pragma unroll
    for (int ki = 0; ki < 16; ++ki) {
        const int cur = ki & 1;
        const int nxt = cur ^ 1;
        if (ki < 15) {
            ldsm4(ah[nxt], aAddrH + (u32)(ki + 1) * 32);
            ldsm4(al[nxt], aAddrL + (u32)(ki + 1) * 32);
            b0[nxt] = bp0[(ki + 1) * 256];
            b1[nxt] = bp1[(ki + 1) * 256];
        }
        mma16816(a0hh, ah[cur], b0[cur].x, b0[cur].y);
        mma16816(a1hh, ah[cur], b1[cur].x, b1[cur].y);
        mma16816(a0hl, ah[cur], b0[cur].z, b0[cur].w);
        mma16816(a1hl, ah[cur], b1[cur].z, b1[cur].w);
        mma16816(a0lh, al[cur], b0[cur].x, b0[cur].y);
        mma16816(a1lh, al[cur], b1[cur].x, b1[cur].y);
    }

    // ---- epilogue: combine terms, scale, add bias-mean ----
    const float inv = 1.f / 256.f;
    const int grow = bid * TILE_M + r0 + g;
    {
        int col = n0 + 2 * t;
        float2 m = *(const float2*)(mb_g + col);
        float s0 = a0hh[0] + a0hl[0] + a0lh[0];
        float s1 = a0hh[1] + a0hl[1] + a0lh[1];
        float s2 = a0hh[2] + a0hl[2] + a0lh[2];
        float s3 = a0hh[3] + a0hl[3] + a0lh[3];
        float2 o0, o1;
        o0.x = fmaf(s0, inv, m.x); o0.y = fmaf(s1, inv, m.y);
        o1.x = fmaf(s2, inv, m.x); o1.y = fmaf(s3, inv, m.y);
        *(float2*)(out + (size_t)grow * ND + col) = o0;
        *(float2*)(out + (size_t)(grow + 8) * ND + col) = o1;
    }
    {
        int col = n0 + 8 + 2 * t;
        float2 m = *(const float2*)(mb_g + col);
        float s0 = a1hh[0] + a1hl[0] + a1lh[0];
        float s1 = a1hh[1] + a1hl[1] + a1lh[1];
        float s2 = a1hh[2] + a1hl[2] + a1lh[2];
        float s3 = a1hh[3] + a1hl[3] + a1lh[3];
        float2 o0, o1;
        o0.x = fmaf(s0, inv, m.x); o0.y = fmaf(s1, inv, m.y);
        o1.x = fmaf(s2, inv, m.x); o1.y = fmaf(s3, inv, m.y);
        *(float2*)(out + (size_t)grow * ND + col) = o0;
        *(float2*)(out + (size_t)(grow + 8) * ND + col) = o1;
    }
}

extern "C" void kernel_launch(void* const* d_in, const int* in_sizes, int n_in,
                              void* d_out, int out_size)
{
    const float* x = (const float*)d_in[0];
    const float* W = (const float*)d_in[1];
    const float* b = (const float*)d_in[2];
    float* out = (float*)d_out;

    prep_kernel<<<17, 256>>>(W, b);

    cudaFuncSetAttribute(nanembed_hmma_kernel,
                         cudaFuncAttributeMaxDynamicSharedMemorySize, SMEM_BYTES);
    cudaLaunchConfig_t cfg = {};
    cfg.gridDim  = dim3(NBLOCKS, 1, 1);
    cfg.blockDim = dim3(MTHREADS, 1, 1);
    cfg.dynamicSmemBytes = SMEM_BYTES;
    cudaLaunchAttribute attrs[1];
    attrs[0].id = cudaLaunchAttributeProgrammaticStreamSerialization;
    attrs[0].val.programmaticStreamSerializationAllowed = 1;
    cfg.attrs = attrs;
    cfg.numAttrs = 1;
    cudaLaunchKernelEx(&cfg, nanembed_hmma_kernel, x, out);
}

// round 11
// speedup vs baseline: 1.0025x; 1.0025x over previous
#include <cuda_runtime.h>
#include <cstdint>

// out[n,d] = mean_f( x[n,f]*W[f,d] + b[f,d] ) = (x@W)[n,d]/256 + mean_f b[f,d]
// N=8192, K=256, D=64. bf16 3-term split on tensor cores (mma.sync m16n8k16).
// prep: W -> Wf fragment table + mb. main (PDL): each CTA streams 4 tiles of
// 16 rows through a double-buffered convert/MMA pipeline; B frags via L1.

typedef uint32_t u32;

#define NROWS  8192
#define NF     256
#define ND     64
#define TILE_M 16
#define MTHREADS 128
#define TPC    4
#define NBLOCKS (NROWS / (TILE_M * TPC))   // 128

#define XPITCHB (264 * 2)                  // 528B padded row
#define XBUF_HL 8448                       // 16 rows * 528B (one of XH/XL)
#define XBUF_BYTES (2 * XBUF_HL)           // 16896 per buffer
#define SMEM_BYTES (2 * XBUF_BYTES)        // 33792

// Wf[ki][col][t] : uint4 {hi(k=2t,2t+1), hi(k=2t+8,2t+9), lo(..), lo(..)}
__device__ uint4 Wf_g[16 * 64 * 4];
__device__ float mb_g[64];

__device__ __forceinline__ u32 smem_u32(const void* p) {
    u32 a;
    asm("{ .reg .u64 t; cvta.to.shared.u64 t, %1; cvt.u32.u64 %0, t; }" : "=r"(a) : "l"(p));
    return a;
}
__device__ __forceinline__ void cvt_split(float a, float b, u32& hi, u32& lo) {
    asm("cvt.rn.bf16x2.f32 %0, %1, %2;" : "=r"(hi) : "f"(b), "f"(a));
    float ha = __uint_as_float(hi << 16);
    float hb = __uint_as_float(hi & 0xFFFF0000u);
    float ra = a - ha;
    float rb = b - hb;
    asm("cvt.rn.bf16x2.f32 %0, %1, %2;" : "=r"(lo) : "f"(rb), "f"(ra));
}
__device__ __forceinline__ void ldsm4(u32* r, u32 addr) {
    asm volatile("ldmatrix.sync.aligned.m8n8.x4.shared.b16 {%0,%1,%2,%3}, [%4];"
        : "=r"(r[0]), "=r"(r[1]), "=r"(r[2]), "=r"(r[3]) : "r"(addr));
}
__device__ __forceinline__ void mma16816(float* c, const u32* a, u32 b0, u32 b1) {
    asm volatile(
        "mma.sync.aligned.m16n8k16.row.col.f32.bf16.bf16.f32 "
        "{%0,%1,%2,%3}, {%4,%5,%6,%7}, {%8,%9}, {%0,%1,%2,%3};"
        : "+f"(c[0]), "+f"(c[1]), "+f"(c[2]), "+f"(c[3])
        : "r"(a[0]), "r"(a[1]), "r"(a[2]), "r"(a[3]), "r"(b0), "r"(b1));
}

// ---------------- prep kernel ----------------
__global__ void __launch_bounds__(256)
prep_kernel(const float* __restrict__ W, const float* __restrict__ b)
{
    const int tid = threadIdx.x;
    if (blockIdx.x < 16) {
        int idx = blockIdx.x * 256 + tid;          // 0..4095
        int ki  = idx >> 8;
        int col = (idx >> 2) & 63;
        int t   = idx & 3;
        int k0  = ki * 16 + 2 * t;
        float w0 = W[(k0    ) * ND + col];
        float w1 = W[(k0 + 1) * ND + col];
        float w2 = W[(k0 + 8) * ND + col];
        float w3 = W[(k0 + 9) * ND + col];
        u32 h01, l01, h23, l23;
        cvt_split(w0, w1, h01, l01);
        cvt_split(w2, w3, h23, l23);
        Wf_g[idx] = make_uint4(h01, h23, l01, l23);
    } else {
        __shared__ float4 sc[256];
        const int qd = tid & 15;
        const int fr = tid >> 4;
        const float4* b4 = (const float4*)b;   // [256][16] float4
        float4 s = make_float4(0.f, 0.f, 0.f, 0.f);
        #pragma unroll
        for (int k = 0; k < 16; ++k) {
            float4 v = b4[(fr * 16 + k) * 16 + qd];
            s.x += v.x; s.y += v.y; s.z += v.z; s.w += v.w;
        }
        sc[tid] = s;
        __syncthreads();
        if (tid < 16) {
            float4 m = make_float4(0.f, 0.f, 0.f, 0.f);
            #pragma unroll
            for (int g = 0; g < 16; ++g) {
                float4 v = sc[tid + 16 * g];
                m.x += v.x; m.y += v.y; m.z += v.z; m.w += v.w;
            }
            const float inv = 1.f / 256.f;
            m.x *= inv; m.y *= inv; m.z *= inv; m.w *= inv;
            ((float4*)mb_g)[tid] = m;
        }
    }
    __threadfence();
    __syncthreads();
    asm volatile("griddepcontrol.launch_dependents;");
}

// ---------------- main kernel ----------------
__global__ void __launch_bounds__(MTHREADS, 4)
nanembed_hmma_kernel(const float* __restrict__ x, float* __restrict__ out)
{
    __shared__ char smem[SMEM_BYTES];
    const u32 sb = smem_u32(smem);
    const int tid = threadIdx.x;
    const int bid = blockIdx.x;
    const int tile0 = bid * TPC;

    // ---- 1) issue x loads for tile 0 (DRAM, in flight) ----
    float4 xv[8];
    {
        const float4* x4 = (const float4*)(x + (size_t)tile0 * TILE_M * NF);
        #pragma unroll
        for (int i = 0; i < 8; ++i)
            xv[i] = x4[tid + MTHREADS * i];
    }

    // ---- 2) PDL wait, then prefetch Wf table into L1 (no regs consumed) ----
    asm volatile("griddepcontrol.wait;");
    {
        const char* wfb = (const char*)Wf_g;
        #pragma unroll
        for (int i = 0; i < 4; ++i) {
            const char* p = wfb + (tid * 4 + i) * 128;   // 512 lines of 128B
            asm volatile("prefetch.global.L1 [%0];" :: "l"(p));
        }
    }

    // ---- warp mapping (constant across tiles) ----
    const int wid  = tid >> 5;
    const int lane = tid & 31;
    const int n0   = wid * 16;
    const int g    = lane >> 2;
    const int t4   = lane & 3;
    const u32 aoff = (u32)(lane & 15) * XPITCHB + (u32)(lane >> 4) * 16;
    const uint4* bp0 = Wf_g + ((n0 + g) * 4 + t4);
    const uint4* bp1 = bp0 + 32;
    const float2 mA = *(const float2*)(mb_g + n0 + 2 * t4);
    const float2 mB = *(const float2*)(mb_g + n0 + 8 + 2 * t4);
    const float inv = 1.f / 256.f;

    // ---- 3) convert tile 0 into buf 0 ----
    #pragma unroll
    for (int i = 0; i < 8; ++i) {
        int idx = tid + MTHREADS * i;       // 0..1023
        int row = idx >> 6;
        int c4  = idx & 63;
        u32 h0, l0, h1, l1;
        cvt_split(xv[i].x, xv[i].y, h0, l0);
        cvt_split(xv[i].z, xv[i].w, h1, l1);
        u32 off = (u32)(row * XPITCHB + c4 * 8);
        asm volatile("st.shared.v2.b32 [%0], {%1, %2};"
                     :: "r"(sb + off), "r"(h0), "r"(h1) : "memory");
        asm volatile("st.shared.v2.b32 [%0], {%1, %2};"
                     :: "r"(sb + XBUF_HL + off), "r"(l0), "r"(l1) : "memory");
    }

    // ---- 4) issue x loads for tile 1 ----
    {
        const float4* x4 = (const float4*)(x + (size_t)(tile0 + 1) * TILE_M * NF);
        #pragma unroll
        for (int i = 0; i < 8; ++i)
            xv[i] = x4[tid + MTHREADS * i];
    }
    __syncthreads();

    // ---- 5) tile loop: mma(t) | conv(t+1) | ldg(t+2) ----
    #pragma unroll 1
    for (int t = 0; t < TPC; ++t) {
        const u32 bufb = sb + (u32)(t & 1) * XBUF_BYTES;
        const u32 aAddrH = bufb + aoff;
        const u32 aAddrL = aAddrH + XBUF_HL;

        float a0hh[4] = {0,0,0,0}, a0hl[4] = {0,0,0,0}, a0lh[4] = {0,0,0,0};
        float a1hh[4] = {0,0,0,0}, a1hl[4] = {0,0,0,0}, a1lh[4] = {0,0,0,0};

        u32 ah[2][4], al[2][4];
        uint4 b0[2], b1[2];
        ldsm4(ah[0], aAddrH);
        ldsm4(al[0], aAddrL);
        b0[0] = bp0[0];
        b1[0] = bp1[0];

        #pragma unroll
        for (int ki = 0; ki < 16; ++ki) {
            const int cur = ki & 1;
            const int nxt = cur ^ 1;
            if (ki < 15) {
                ldsm4(ah[nxt], aAddrH + (u32)(ki + 1) * 32);
                ldsm4(al[nxt], aAddrL + (u32)(ki + 1) * 32);
                b0[nxt] = bp0[(ki + 1) * 256];
                b1[nxt] = bp1[(ki + 1) * 256];
            }
            mma16816(a0hh, ah[cur], b0[cur].x, b0[cur].y);
            mma16816(a1hh, ah[cur], b1[cur].x, b1[cur].y);
            mma16816(a0hl, ah[cur], b0[cur].z, b0[cur].w);
            mma16816(a1hl, ah[cur], b1[cur].z, b1[cur].w);
            mma16816(a0lh, al[cur], b0[cur].x, b0[cur].y);
            mma16816(a1lh, al[cur], b1[cur].x, b1[cur].y);
        }

        // ---- epilogue for tile t ----
        {
            const int grow = (tile0 + t) * TILE_M + g;
            int col = n0 + 2 * t4;
            float s0 = a0hh[0] + a0hl[0] + a0lh[0];
            float s1 = a0hh[1] + a0hl[1] + a0lh[1];
            float s2 = a0hh[2] + a0hl[2] + a0lh[2];
            float s3 = a0hh[3] + a0hl[3] + a0lh[3];
            float2 o0, o1;
            o0.x = fmaf(s0, inv, mA.x); o0.y = fmaf(s1, inv, mA.y);
            o1.x = fmaf(s2, inv, mA.x); o1.y = fmaf(s3, inv, mA.y);
            *(float2*)(out + (size_t)grow * ND + col) = o0;
            *(float2*)(out + (size_t)(grow + 8) * ND + col) = o1;

            col = n0 + 8 + 2 * t4;
            s0 = a1hh[0] + a1hl[0] + a1lh[0];
            s1 = a1hh[1] + a1hl[1] + a1lh[1];
            s2 = a1hh[2] + a1hl[2] + a1lh[2];
            s3 = a1hh[3] + a1hl[3] + a1lh[3];
            o0.x = fmaf(s0, inv, mB.x); o0.y = fmaf(s1, inv, mB.y);
            o1.x = fmaf(s2, inv, mB.x); o1.y = fmaf(s3, inv, mB.y);
            *(float2*)(out + (size_t)grow * ND + col) = o0;
            *(float2*)(out + (size_t)(grow + 8) * ND + col) = o1;
        }

        if (t < TPC - 1) {
            // convert tile t+1 into the other buffer
            const u32 nbufb = sb + (u32)((t + 1) & 1) * XBUF_BYTES;
            #pragma unroll
            for (int i = 0; i < 8; ++i) {
                int idx = tid + MTHREADS * i;
                int row = idx >> 6;
                int c4  = idx & 63;
                u32 h0, l0, h1, l1;
                cvt_split(xv[i].x, xv[i].y, h0, l0);
                cvt_split(xv[i].z, xv[i].w, h1, l1);
                u32 off = (u32)(row * XPITCHB + c4 * 8);
                asm volatile("st.shared.v2.b32 [%0], {%1, %2};"
                             :: "r"(nbufb + off), "r"(h0), "r"(h1) : "memory");
                asm volatile("st.shared.v2.b32 [%0], {%1, %2};"
                             :: "r"(nbufb + XBUF_HL + off), "r"(l0), "r"(l1) : "memory");
            }
            // issue x loads for tile t+2
            if (t < TPC - 2) {
                const float4* x4 = (const float4*)(x + (size_t)(tile0 + t + 2) * TILE_M * NF);
                #pragma unroll
                for (int i = 0; i < 8; ++i)
                    xv[i] = x4[tid + MTHREADS * i];
            }
            __syncthreads();
        }
    }
}

extern "C" void kernel_launch(void* const* d_in, const int* in_sizes, int n_in,
                              void* d_out, int out_size)
{
    const float* x = (const float*)d_in[0];
    const float* W = (const float*)d_in[1];
    const float* b = (const float*)d_in[2];
    float* out = (float*)d_out;

    prep_kernel<<<17, 256>>>(W, b);

    cudaLaunchConfig_t cfg = {};
    cfg.gridDim  = dim3(NBLOCKS, 1, 1);
    cfg.blockDim = dim3(MTHREADS, 1, 1);
    cfg.dynamicSmemBytes = 0;
    cudaLaunchAttribute attrs[1];
    attrs[0].id = cudaLaunchAttributeProgrammaticStreamSerialization;
    attrs[0].val.programmaticStreamSerializationAllowed = 1;
    cfg.attrs = attrs;
    cfg.numAttrs = 1;
    cudaLaunchKernelEx(&cfg, nanembed_hmma_kernel, x, out);
}